// round 17
// baseline (speedup 1.0000x reference)
#include <cuda_runtime.h>
#include <cuda_fp16.h>
#include <cstdint>
#include <math.h>

typedef __half f16;

// ===========================================================================
// TriParser, fp16 HMMA (f32 accum).
//   build_h16: h -> hi|lo f16 [1024,1024];  prep: Up rows r=d*256+c [65536,256],
//   Wp split [256,1024];  upfrag: Up -> B-fragment layout UpF.
//   proj (split 3-product HMMA): elu(h@W+b) -> f16 [1024,256]
//   stage1: t1 = u @ Up^T   (A resident smem; B frags via direct LDG, NO syncs)
//   stage2: t2 = v[b] @ t1^T;  stage3: s = t2 @ w[b]^T (f32)
// ===========================================================================

__device__ f16 g_h16[1024 * 1024];                     // 2 MB
__device__ f16 g_Wp[7 * 256 * 1024];                   // 3.5 MB
__device__ f16 g_projb[7 * 1024 * 256];                // 3.5 MB
__device__ f16 g_Up[3ull * 65536 * 256];               // 96 MB (row layout)
__device__ f16 g_UpF[3ull * 65536 * 256];              // 96 MB (fragment layout)
__device__ f16 g_t1[3ull * 1024 * 65536];              // 402 MB
__device__ f16 g_t2[3ull * 1024 * 128 * 256];          // 201 MB

static const size_t PB  = 1024 * 256;
static const size_t PBW = 256 * 1024;
static const size_t UPS = (size_t)65536 * 256;
static const size_t T1S = (size_t)1024 * 65536;
static const size_t T2S = (size_t)1024 * 32768;

__device__ __forceinline__ uint32_t smem_u32(const void* p) {
    uint32_t a;
    asm("{ .reg .u64 t; cvta.to.shared.u64 t, %1; cvt.u32.u64 %0, t; }"
        : "=r"(a) : "l"(p));
    return a;
}

#define SW128(o) ((o) ^ (((o) >> 3) & 0x70))

__device__ __forceinline__ void ldm_x4(uint32_t* r, uint32_t addr) {
    asm volatile("ldmatrix.sync.aligned.m8n8.x4.shared.b16 {%0,%1,%2,%3}, [%4];"
                 : "=r"(r[0]), "=r"(r[1]), "=r"(r[2]), "=r"(r[3]) : "r"(addr));
}

__device__ __forceinline__ void mma16816(float* c, const uint32_t* a, const uint32_t* b) {
    asm volatile(
        "mma.sync.aligned.m16n8k16.row.col.f32.f16.f16.f32 "
        "{%0,%1,%2,%3}, {%4,%5,%6,%7}, {%8,%9}, {%0,%1,%2,%3};"
        : "+f"(c[0]), "+f"(c[1]), "+f"(c[2]), "+f"(c[3])
        : "r"(a[0]), "r"(a[1]), "r"(a[2]), "r"(a[3]), "r"(b[0]), "r"(b[1]));
}

__device__ __forceinline__ void cpa16(uint32_t dst, const void* src) {
    asm volatile("cp.async.cg.shared.global [%0], [%1], 16;" :: "r"(dst), "l"(src) : "memory");
}
#define CP_COMMIT() asm volatile("cp.async.commit_group;" ::: "memory")
#define CP_WAIT1()  asm volatile("cp.async.wait_group 1;" ::: "memory")
#define CP_WAIT0()  asm volatile("cp.async.wait_group 0;" ::: "memory")

// PLAIN K64 tile, 128 rows (16KB), NT threads.
template <int NT>
__device__ __forceinline__ void load_plain(const f16* __restrict__ g, int rs, int c64,
                                           uint32_t dst, int tid) {
#pragma unroll
    for (int i = 0; i < 1024 / NT; i++) {
        int idx = tid + i * NT;
        int row = idx >> 3, seg = idx & 7;
        cpa16(dst + SW128(row * 128 + seg * 16), g + (size_t)row * rs + c64 * 64 + seg * 8);
    }
}

// SPLIT K32 tile (16KB), NT threads.
template <int NT>
__device__ __forceinline__ void load_split(const f16* __restrict__ g, int rs, int loOff,
                                           int c32, uint32_t dst, int tid) {
#pragma unroll
    for (int i = 0; i < 1024 / NT; i++) {
        int idx = tid + i * NT;
        int row = idx >> 3, seg = idx & 7;
        int col = (seg < 4) ? c32 * 32 + seg * 8 : loOff + c32 * 32 + (seg - 4) * 8;
        cpa16(dst + SW128(row * 128 + seg * 16), g + (size_t)row * rs + col);
    }
}

// One K64 unit, 64x64 warp tile (MI=4), both operands smem (stages 2/3).
__device__ __forceinline__ void mma_unit4(uint32_t ab, uint32_t bb,
                                          float (&acc)[4][8][4],
                                          int aLB, int bLB, int wm, int wn) {
#pragma unroll
    for (int kk = 0; kk < 4; kk++) {
        uint32_t aq[4][4], bq[4][4];
#pragma unroll
        for (int mi = 0; mi < 4; mi++) {
            int off = aLB + (wm * 64 + mi * 16) * 128 + kk * 32;
            ldm_x4(aq[mi], ab + SW128(off));
        }
#pragma unroll
        for (int nj = 0; nj < 4; nj++) {
            int off = bLB + (wn * 64 + nj * 16) * 128 + kk * 32;
            ldm_x4(bq[nj], bb + SW128(off));
        }
#pragma unroll
        for (int mi = 0; mi < 4; mi++)
#pragma unroll
            for (int nj = 0; nj < 4; nj++) {
                mma16816(acc[mi][nj * 2],     aq[mi], &bq[nj][0]);
                mma16816(acc[mi][nj * 2 + 1], aq[mi], &bq[nj][2]);
            }
    }
}

#define ZERO_ACC4(acc) \
    { _Pragma("unroll") for (int i = 0; i < 4; i++) \
      _Pragma("unroll") for (int j = 0; j < 8; j++) \
      _Pragma("unroll") for (int k = 0; k < 4; k++) acc[i][j][k] = 0.0f; }

#define WARP_IDS \
    const int tid = threadIdx.x; \
    const int lane = tid & 31; \
    const int warp = tid >> 5; \
    const int wm = warp >> 1, wn = warp & 1; \
    const int aLB = ((lane & 15) * 128) + ((lane >> 4) * 16); \
    const int bLB = (((lane & 7) + ((lane >> 4) << 3)) * 128) + (((lane >> 3) & 1) * 16); \
    const int gRow = lane >> 2; \
    const int cPair = (lane & 3) * 2;

// ===========================================================================
// upfrag: Up row layout -> B-fragment layout.
// Per (tri, nt): src 128 r x 256 a; dst blocks blk = ks*16+g (256 x 128 f16):
//   lane l: f16[4] = { Up[g*8+l/4][ks*16+2(l%4)], +1, +8, +9 }
// ===========================================================================
__global__ __launch_bounds__(256)
void upfrag_k(const f16* __restrict__ Up, f16* __restrict__ UpF)
{
    __shared__ f16 S[128][264];   // pad 264 -> conflict-free gather
    const int bid = blockIdx.x;               // 0..1535
    const int tri = bid >> 9, nt = bid & 511;
    const f16* src = Up + (size_t)tri * UPS + (size_t)nt * 128 * 256;
    f16* dst = UpF + (size_t)tri * UPS + (size_t)nt * 32768;
    const int tid = threadIdx.x;

#pragma unroll
    for (int i = 0; i < 16; i++) {
        int idx = tid + i * 256;               // 4096 uint4
        int r = idx >> 5, cc = idx & 31;
        *(uint4*)&S[r][cc * 8] = *(const uint4*)(src + (size_t)r * 256 + cc * 8);
    }
    __syncthreads();

    const int w = tid >> 5, lane = tid & 31;
#pragma unroll
    for (int i = 0; i < 32; i++) {
        int blk = w * 32 + i;                  // = ks*16 + g
        int ks = blk >> 4, g = blk & 15;
        int r = g * 8 + (lane >> 2);
        int a0 = ks * 16 + 2 * (lane & 3);
        uint2 v;
        v.x = *(const uint32_t*)&S[r][a0];
        v.y = *(const uint32_t*)&S[r][a0 + 8];
        *(uint2*)(dst + (size_t)blk * 128 + lane * 4) = v;
    }
}

// ===========================================================================
// Stage1 (all tris): t1 = u @ Up^T. grid (8 M, 64 Ngrp, 3 tri), 128 thr.
// A [128x256] resident smem; B fragments via direct LDG (ring depth 2).
// NO __syncthreads in the main loop.
// ===========================================================================
__global__ __launch_bounds__(128, 2)
void stage1_k(const f16* __restrict__ projb, const f16* __restrict__ UpF,
              f16* __restrict__ T1)
{
    extern __shared__ char dsm[];
    const uint32_t sraw = smem_u32(dsm);
    const uint32_t sbA = (sraw + 1023u) & ~1023u;

    WARP_IDS

    const int tri = blockIdx.z;
    const f16* Au = projb + (size_t)(2 * tri) * PB + (size_t)blockIdx.x * 128 * 256;
    f16* T1t = T1 + (size_t)tri * T1S;
    // linear fragment stream: step s in [0,128): block row s covers (nt=s>>4, ks=s&15)
    const f16* BFlin = UpF + (size_t)tri * UPS + (size_t)blockIdx.y * 8 * 32768
                       + wn * 1024 + lane * 4;

    uint32_t bbuf[2][16];
    auto ldB = [&](int s, uint32_t (&d)[16]) {
        if (s < 128) {
            const f16* p = BFlin + (size_t)s * 2048;
#pragma unroll
            for (int q = 0; q < 8; q++) {
                uint2 v = *(const uint2*)(p + q * 128);
                d[q * 2] = v.x; d[q * 2 + 1] = v.y;
            }
        }
    };

    // resident A
#pragma unroll
    for (int ch = 0; ch < 4; ch++)
        load_plain<128>(Au, 256, ch, sbA + ch * 16384, tid);
    CP_COMMIT();
    ldB(0, bbuf[0]);
    ldB(1, bbuf[1]);
    CP_WAIT0();
    __syncthreads();

    float acc[4][8][4];
    ZERO_ACC4(acc);

    for (int nt = 0; nt < 8; nt++) {
#pragma unroll
        for (int ss = 0; ss < 16; ss++) {
            const int s = nt * 16 + ss;
            uint32_t aq[4][4];
#pragma unroll
            for (int mi = 0; mi < 4; mi++) {
                int off = aLB + (wm * 64 + mi * 16) * 128 + (ss & 3) * 32;
                ldm_x4(aq[mi], sbA + (ss >> 2) * 16384 + SW128(off));
            }
            uint32_t (&bq)[16] = bbuf[ss & 1];
#pragma unroll
            for (int mi = 0; mi < 4; mi++)
#pragma unroll
                for (int nj = 0; nj < 4; nj++) {
                    mma16816(acc[mi][nj * 2],     aq[mi], &bq[(nj * 2) * 2]);
                    mma16816(acc[mi][nj * 2 + 1], aq[mi], &bq[(nj * 2 + 1) * 2]);
                }
            ldB(s + 2, bbuf[ss & 1]);
        }
        // epilogue for N-tile nt
        size_t colBase = ((size_t)blockIdx.y * 8 + nt) * 128;
#pragma unroll
        for (int mi = 0; mi < 4; mi++) {
            int rbase = blockIdx.x * 128 + wm * 64 + mi * 16 + gRow;
#pragma unroll
            for (int f = 0; f < 8; f++) {
                int nloc = wn * 64 + f * 8 + cPair;
#pragma unroll
                for (int hh = 0; hh < 2; hh++) {
                    size_t row = (size_t)(rbase + hh * 8);
                    __half2 p;
                    p.x = __float2half(acc[mi][f][hh * 2 + 0]);
                    p.y = __float2half(acc[mi][f][hh * 2 + 1]);
                    *(__half2*)(T1t + row * 65536 + colBase + nloc) = p;
                    acc[mi][f][hh * 2 + 0] = 0.0f;
                    acc[mi][f][hh * 2 + 1] = 0.0f;
                }
            }
        }
    }
}

// ===========================================================================
// Stage2 (all tris): t2 = v[b] @ t1^T. 2 tokens/CTA, grid (512,3), 128 thr.
// ===========================================================================
struct Ptr3 { const f16* p[3]; };

__global__ __launch_bounds__(128, 2)
void stage2_k(Ptr3 vp, const f16* __restrict__ T1, f16* __restrict__ T2)
{
    extern __shared__ char dsm[];
    const uint32_t sraw = smem_u32(dsm);
    const uint32_t sb = (sraw + 1023u) & ~1023u;
    const uint32_t sbA = sb;
    const uint32_t sbB = sb + 65536;

    WARP_IDS

    const int z = blockIdx.x;
    const int tri = blockIdx.y;
    const f16* Av = vp.p[tri] + (size_t)(z >> 6) * 32768;
    const f16* T1t = T1 + (size_t)tri * T1S;
    f16* T2t = T2 + (size_t)tri * T2S;

    auto issueU = [&](int g) {
        if (g < 16) {
            int tt = g >> 3, nh = (g >> 2) & 1, ch = g & 3;
            const f16* src = T1t + (size_t)(2 * z + tt) * 65536 + (size_t)nh * 128 * 256;
            load_plain<128>(src, 256, ch, sbB + (g % 3) * 16384, tid);
        }
        CP_COMMIT();
    };

#pragma unroll
    for (int ch = 0; ch < 4; ch++)
        load_plain<128>(Av, 256, ch, sbA + ch * 16384, tid);
    issueU(0);
    issueU(1);

    float acc[4][8][4];
    ZERO_ACC4(acc);

#pragma unroll
    for (int g = 0; g < 16; g++) {
        if (g < 15) CP_WAIT1(); else CP_WAIT0();
        __syncthreads();
        issueU(g + 2);
        mma_unit4(sbA + (g & 3) * 16384, sbB + (g % 3) * 16384, acc, aLB, bLB, wm, wn);

        if ((g & 3) == 3) {
            int tt = g >> 3, nh = (g >> 2) & 1;
            f16* Cb = T2t + (size_t)(2 * z + tt) * 32768;
#pragma unroll
            for (int mi = 0; mi < 4; mi++) {
                int rbase = wm * 64 + mi * 16 + gRow;
#pragma unroll
                for (int f = 0; f < 8; f++) {
                    int col = nh * 128 + wn * 64 + f * 8 + cPair;
#pragma unroll
                    for (int hh = 0; hh < 2; hh++) {
                        size_t row = (size_t)(rbase + hh * 8);
                        __half2 p;
                        p.x = __float2half(acc[mi][f][hh * 2 + 0]);
                        p.y = __float2half(acc[mi][f][hh * 2 + 1]);
                        *(__half2*)(Cb + row * 256 + col) = p;
                        acc[mi][f][hh * 2 + 0] = 0.0f;
                        acc[mi][f][hh * 2 + 1] = 0.0f;
                    }
                }
            }
        }
    }
}

// ===========================================================================
// Stage3 (all tris): s = t2 @ w[b]^T. 2 tokens/CTA, grid (512,3), f32 out.
// ===========================================================================
__global__ __launch_bounds__(128, 2)
void stage3_k(Ptr3 wp, const f16* __restrict__ T2, float* __restrict__ OUT)
{
    extern __shared__ char dsm[];
    const uint32_t sraw = smem_u32(dsm);
    const uint32_t sb = (sraw + 1023u) & ~1023u;
    const uint32_t sbB = sb;
    const uint32_t sbA = sb + 65536;

    WARP_IDS

    const int z = blockIdx.x;
    const int tri = blockIdx.y;
    const f16* Bw = wp.p[tri] + (size_t)(z >> 6) * 32768;
    const f16* T2t = T2 + (size_t)tri * T2S;
    float* Ot = OUT + (size_t)tri * 16777216;

    auto issueA = [&](int g) {
        if (g < 8) {
            int tt = g >> 2, ch = g & 3;
            load_plain<128>(T2t + (size_t)(2 * z + tt) * 32768, 256, ch,
                            sbA + (g % 3) * 16384, tid);
        }
        CP_COMMIT();
    };

#pragma unroll
    for (int ch = 0; ch < 4; ch++)
        load_plain<128>(Bw, 256, ch, sbB + ch * 16384, tid);
    issueA(0);
    issueA(1);

    float acc[4][8][4];
    ZERO_ACC4(acc);

#pragma unroll
    for (int g = 0; g < 8; g++) {
        if (g < 7) CP_WAIT1(); else CP_WAIT0();
        __syncthreads();
        issueA(g + 2);
        mma_unit4(sbA + (g % 3) * 16384, sbB + (g & 3) * 16384, acc, aLB, bLB, wm, wn);

        if ((g & 3) == 3) {
            int tt = g >> 2;
            float* Cb = Ot + (size_t)(2 * z + tt) * 16384;
#pragma unroll
            for (int mi = 0; mi < 4; mi++) {
                int rbase = wm * 64 + mi * 16 + gRow;
#pragma unroll
                for (int f = 0; f < 8; f++) {
                    int col = wn * 64 + f * 8 + cPair;
#pragma unroll
                    for (int hh = 0; hh < 2; hh++) {
                        size_t row = (size_t)(rbase + hh * 8);
                        *(float2*)(Cb + row * 128 + col) =
                            make_float2(acc[mi][f][hh * 2 + 0], acc[mi][f][hh * 2 + 1]);
                        acc[mi][f][hh * 2 + 0] = 0.0f;
                        acc[mi][f][hh * 2 + 1] = 0.0f;
                    }
                }
            }
        }
    }
}

// ===========================================================================
// Projection, split 3-product HMMA: elu(h@W+b) -> f16 [1024,256]
// ===========================================================================
struct BiasArgs { const float* b[7]; };

__global__ __launch_bounds__(256, 2)
void proj_mma(BiasArgs ba, const f16* __restrict__ h16, const f16* __restrict__ Wp,
              f16* __restrict__ projb)
{
    extern __shared__ char dsm[];
    const uint32_t sraw = smem_u32(dsm);
    const uint32_t sb = (sraw + 1023u) & ~1023u;

    WARP_IDS

    const int br = blockIdx.z;
    const f16* A = h16 + (size_t)blockIdx.x * 128 * 1024;
    const f16* B = Wp + (size_t)br * PBW + (size_t)blockIdx.y * 128 * 1024;

    auto issue = [&](int s) {
        if (s < 16) {
            uint32_t buf = sb + (s & 1) * 32768;
            load_split<256>(A, 1024, 512, s, buf, tid);
            load_split<256>(B, 1024, 512, s, buf + 16384, tid);
        }
        CP_COMMIT();
    };
    issue(0); issue(1);

    float acc[2][8][4];
#pragma unroll
    for (int i = 0; i < 2; i++)
#pragma unroll
        for (int j = 0; j < 8; j++)
#pragma unroll
            for (int k = 0; k < 4; k++) acc[i][j][k] = 0.0f;

#pragma unroll
    for (int s = 0; s < 16; s++) {
        if (s < 15) CP_WAIT1(); else CP_WAIT0();
        __syncthreads();
        uint32_t ab = sb + (s & 1) * 32768;
        uint32_t bb = ab + 16384;
#pragma unroll
        for (int kk = 0; kk < 2; kk++) {
            uint32_t ah[2][4], al[2][4], bh[4][4], bl[4][4];
#pragma unroll
            for (int mi = 0; mi < 2; mi++) {
                int off = aLB + (wm * 32 + mi * 16) * 128 + kk * 32;
                ldm_x4(ah[mi], ab + SW128(off));
                ldm_x4(al[mi], ab + SW128(off + 64));
            }
#pragma unroll
            for (int nj = 0; nj < 4; nj++) {
                int off = bLB + (wn * 64 + nj * 16) * 128 + kk * 32;
                ldm_x4(bh[nj], bb + SW128(off));
                ldm_x4(bl[nj], bb + SW128(off + 64));
            }
#pragma unroll
            for (int mi = 0; mi < 2; mi++)
#pragma unroll
                for (int nj = 0; nj < 4; nj++) {
                    mma16816(acc[mi][nj * 2],     ah[mi], &bh[nj][0]);
                    mma16816(acc[mi][nj * 2 + 1], ah[mi], &bh[nj][2]);
                    mma16816(acc[mi][nj * 2],     ah[mi], &bl[nj][0]);
                    mma16816(acc[mi][nj * 2 + 1], ah[mi], &bl[nj][2]);
                    mma16816(acc[mi][nj * 2],     al[mi], &bh[nj][0]);
                    mma16816(acc[mi][nj * 2 + 1], al[mi], &bh[nj][2]);
                }
        }
        if (s < 14) { __syncthreads(); issue(s + 2); }
    }

    const float* bias = ba.b[br];
    f16* Co = projb + (size_t)br * PB;
#pragma unroll
    for (int mi = 0; mi < 2; mi++) {
        int rbase = blockIdx.x * 128 + wm * 32 + mi * 16 + gRow;
#pragma unroll
        for (int f = 0; f < 8; f++) {
            int col = blockIdx.y * 128 + wn * 64 + f * 8 + cPair;
#pragma unroll
            for (int hh = 0; hh < 2; hh++) {
                int row = rbase + hh * 8;
                float v0 = acc[mi][f][hh * 2 + 0] + bias[col];
                float v1 = acc[mi][f][hh * 2 + 1] + bias[col + 1];
                v0 = v0 > 0.f ? v0 : expm1f(v0);
                v1 = v1 > 0.f ? v1 : expm1f(v1);
                __half2 p;
                p.x = __float2half(v0);
                p.y = __float2half(v1);
                *(__half2*)(Co + (size_t)row * 256 + col) = p;
            }
        }
    }
}

// ===========================================================================
// Prep kernel: z < 768 -> Up permute; z >= 768 -> W transpose+split.
// ===========================================================================
struct PtrU { const float* p[3]; };
struct PtrW { const float* p[7]; };

__global__ void prep_k(PtrU Us, f16* __restrict__ Up, PtrW Ws, f16* __restrict__ Wp)
{
    __shared__ float t[32][33];
    const int zz = blockIdx.z;
    const int tx = threadIdx.x;
    const int ty = threadIdx.y;

    if (zz < 768) {
        const int tri = zz >> 8;
        const int c = zz & 255;
        const float* U = Us.p[tri];
        f16* Upt = Up + (size_t)tri * UPS;
        const int d0 = blockIdx.x * 32;
        const int a0 = blockIdx.y * 32;
#pragma unroll
        for (int i = 0; i < 32; i += 8)
            t[ty + i][tx] = U[(size_t)(a0 + ty + i) * 65536 + c * 256 + d0 + tx];
        __syncthreads();
#pragma unroll
        for (int i = 0; i < 32; i += 8) {
            int dl = ty + i;
            size_t rowbase = ((size_t)(d0 + dl) * 256 + c) * 256;
            Upt[rowbase + a0 + tx] = __float2half(t[tx][dl]);
        }
    } else {
        const int br = zz - 768;
        const float* W = Ws.p[br];
        f16* Wpt = Wp + (size_t)br * PBW;
        for (int t2i = 0; t2i < 2; t2i++) {
            int tile = ((blockIdx.y * 8 + blockIdx.x) * 2 + t2i);
            int k0 = (tile >> 3) * 32;
            int n0 = (tile & 7) * 32;
            __syncthreads();
#pragma unroll
            for (int i = 0; i < 32; i += 8)
                t[ty + i][tx] = W[(size_t)(k0 + ty + i) * 256 + n0 + tx];
            __syncthreads();
#pragma unroll
            for (int i = 0; i < 32; i += 8) {
                int dl = ty + i;
                float v = t[tx][dl];
                f16 hb = __float2half(v);
                f16 lb = __float2half(v - __half2float(hb));
                size_t rowbase = (size_t)(n0 + dl) * 1024;
                Wpt[rowbase + k0 + tx] = hb;
                Wpt[rowbase + 512 + k0 + tx] = lb;
            }
        }
    }
}

__global__ void build_h16(const float* __restrict__ x, const float* __restrict__ sent,
                          f16* __restrict__ h16)
{
    int idx = blockIdx.x * blockDim.x + threadIdx.x;
    int rowi = idx >> 9;
    int e = idx & 511;
    int t = rowi & 127;
    int b = rowi >> 7;
    float v = (t == 0) ? sent[e] : x[((size_t)(b * 127 + t - 1)) * 512 + e];
    f16 hb = __float2half(v);
    f16 lb = __float2half(v - __half2float(hb));
    h16[(size_t)rowi * 1024 + e] = hb;
    h16[(size_t)rowi * 1024 + 512 + e] = lb;
}

__global__ void write_mask(const int* __restrict__ mask, float* __restrict__ outm)
{
    int i = blockIdx.x * blockDim.x + threadIdx.x;
    if (i < 1024) {
        int b = i >> 7, t = i & 127;
        outm[i] = (t == 0) ? 1.0f : (float)mask[b * 127 + t - 1];
    }
}

// ===========================================================================
extern "C" void kernel_launch(void* const* d_in, const int* in_sizes, int n_in,
                              void* d_out, int out_size)
{
    (void)in_sizes; (void)n_in; (void)out_size;

    const float* x    = (const float*)d_in[0];
    const int*   mask = (const int*)d_in[2];
    const float* sent = (const float*)d_in[20];
    float* out = (float*)d_out;

    f16 *h16, *Wpb, *projb, *Up, *UpF, *t1, *t2;
    cudaGetSymbolAddress((void**)&h16,   g_h16);
    cudaGetSymbolAddress((void**)&Wpb,   g_Wp);
    cudaGetSymbolAddress((void**)&projb, g_projb);
    cudaGetSymbolAddress((void**)&Up,    g_Up);
    cudaGetSymbolAddress((void**)&UpF,   g_UpF);
    cudaGetSymbolAddress((void**)&t1,    g_t1);
    cudaGetSymbolAddress((void**)&t2,    g_t2);

    const int SMEM1 = 65536 + 1024;               // stage1: resident A only
    const int SMEM  = 65536 + 3 * 16384 + 1024;   // stage2/3
    const int SMEMP = 2 * 32768 + 1024;           // proj
    cudaFuncSetAttribute(stage1_k, cudaFuncAttributeMaxDynamicSharedMemorySize, SMEM1);
    cudaFuncSetAttribute(stage2_k, cudaFuncAttributeMaxDynamicSharedMemorySize, SMEM);
    cudaFuncSetAttribute(stage3_k, cudaFuncAttributeMaxDynamicSharedMemorySize, SMEM);
    cudaFuncSetAttribute(proj_mma, cudaFuncAttributeMaxDynamicSharedMemorySize, SMEMP);

    BiasArgs ba;
    PtrW ws;
    for (int i = 0; i < 7; i++) {
        ws.p[i] = (const float*)d_in[3 + 2 * i];
        ba.b[i] = (const float*)d_in[4 + 2 * i];
    }
    PtrU us;
    us.p[0] = (const float*)d_in[17];
    us.p[1] = (const float*)d_in[18];
    us.p[2] = (const float*)d_in[19];

    Ptr3 vp = {{ projb + 1 * PB, projb + 3 * PB, projb + 6 * PB }};
    Ptr3 wp = {{ projb + 1 * PB, projb + 2 * PB, projb + 5 * PB }};

    build_h16<<<2048, 256>>>(x, sent, h16);                          // 0
    prep_k<<<dim3(8, 8, 775), dim3(32, 8)>>>(us, Up, ws, Wpb);       // 1
    proj_mma<<<dim3(8, 2, 7), 256, SMEMP>>>(ba, h16, Wpb, projb);    // 2
    upfrag_k<<<1536, 256>>>(Up, UpF);                                // 3
    stage1_k<<<dim3(8, 64, 3), 128, SMEM1>>>(projb, UpF, t1);        // 4
    stage2_k<<<dim3(512, 3), 128, SMEM>>>(vp, t1, t2);               // 5
    stage3_k<<<dim3(512, 3), 128, SMEM>>>(wp, t2, out);              // 6
    write_mask<<<4, 256>>>(mask, out + (size_t)3 * 16777216);        // 7
}